// round 1
// baseline (speedup 1.0000x reference)
#include <cuda_runtime.h>
#include <math.h>

// Problem dims
#define BATCH 16384
#define FF    50
#define EE    64
#define FE    3200      // F*E
#define DD    512
#define NPAIR 1275      // F*(F+1)/2
#define KPAD  1280      // NPAIR padded to mult of 16
#define HH1   1024
#define HH2   512

// ---------------- scratch (device globals; no allocation allowed) ----------
__device__ float g_emb [(size_t)BATCH * FE];     // 210 MB
__device__ float g_gram[(size_t)BATCH * KPAD];   // 84 MB
__device__ float g_R   [(size_t)DD * KPAD];
__device__ float g_lz  [(size_t)BATCH * DD];
__device__ float g_y0  [(size_t)BATCH * DD];
__device__ float g_y1  [(size_t)BATCH * HH1];
__device__ float g_y2  [(size_t)BATCH * HH2];
__device__ float g_pS  [128 * HH1];              // BN partial sums (grid.y=128)
__device__ float g_pQ  [128 * HH1];
__device__ float g_bnA1[HH1], g_bnB1[HH1];
__device__ float g_bnA2[HH2], g_bnB2[HH2];

// p -> (f1,f2) with f1<=f2, row-major upper triangle
__device__ __forceinline__ void pair_of(int p, int& f1, int& f2) {
    int a = 0, rem = p;
    while (rem >= FF - a) { rem -= FF - a; a++; }
    f1 = a; f2 = a + rem;
}

// ---------------- K1: embedding gather ------------------------------------
// emb[b,f,e] = femb[idx[b,f], e] * val[b,f]
__global__ void embed_kernel(const int* __restrict__ fidx,
                             const float* __restrict__ fval,
                             const float* __restrict__ femb) {
    int t = threadIdx.x;
    int e = t & 63;
    int row = blockIdx.x * 4 + (t >> 6);      // row in [0, BATCH*FF)
    int i = fidx[row];
    float v = fval[row];
    g_emb[(size_t)row * EE + e] = femb[(size_t)i * EE + e] * v;
}

// ---------------- K2: Gram matrices G[b, p] = <emb_b[f1,:], emb_b[f2,:]> ---
__global__ void gram_kernel() {
    __shared__ float es[FF * 65];              // pad 65 to avoid bank conflicts
    int b = blockIdx.x;
    const float* src = g_emb + (size_t)b * FE;
    for (int t = threadIdx.x; t < FE; t += 256) {
        int f = t >> 6, e = t & 63;
        es[f * 65 + e] = src[t];
    }
    __syncthreads();
    float* dst = g_gram + (size_t)b * KPAD;
    for (int p = threadIdx.x; p < KPAD; p += 256) {
        float s = 0.f;
        if (p < NPAIR) {
            int f1, f2; pair_of(p, f1, f2);
            const float* r1 = es + f1 * 65;
            const float* r2 = es + f2 * 65;
            #pragma unroll
            for (int e = 0; e < EE; e++) s += r1[e] * r2[e];
        }
        dst[p] = s;
    }
}

// ---------------- K3: R[d,p] = q[d,f1]*q[d,f2]*(f1==f2 ? 1 : 2) ------------
__global__ void rk_kernel(const float* __restrict__ q) {
    int d = blockIdx.x;
    const float* qd = q + d * FF;
    float* dst = g_R + (size_t)d * KPAD;
    for (int p = threadIdx.x; p < KPAD; p += 256) {
        float v = 0.f;
        if (p < NPAIR) {
            int f1, f2; pair_of(p, f1, f2);
            v = qd[f1] * qd[f2] * ((f1 == f2) ? 1.f : 2.f);
        }
        dst[p] = v;
    }
}

// ---------------- generic tiled SGEMM --------------------------------------
// C(M x N) = op(A)(M x K) @ op(B)(K x N)
// MODEB: 0 -> B stored [N][K] row-major (ldb = K)   (weights like PL, R)
//        1 -> B stored [K][N] row-major (ldb = N)   (layer_0, layer_1)
// EPI:   0 -> plain store
//        1 -> y0 combine: C = relu(lz + sqrt(max(acc,0)) + pbias)
//        2 -> C = acc + bias[n]; write per-block column partial sum/sumsq
// ABN:   apply per-k BN+relu to A elements on load: a = relu(a*aA[k]+aB[k])
#define BM 128
#define BN 128
#define BK 16

template<int MODEB, int EPI, bool ABN>
__global__ __launch_bounds__(256, 2)
void gemm_kernel(const float* __restrict__ A, const float* __restrict__ Bm,
                 float* __restrict__ C, int N, int K, int lda, int ldb,
                 const float* __restrict__ aA, const float* __restrict__ aB,
                 const float* __restrict__ bias,
                 const float* __restrict__ lzp, const float* __restrict__ pbias,
                 float* __restrict__ statS, float* __restrict__ statQ) {
    __shared__ float As[BK][BM];
    __shared__ float Bs[BK][BN];

    const int tid = threadIdx.x;
    const int tx = tid & 15;        // n direction
    const int ty = tid >> 4;        // m direction
    const int m0 = blockIdx.y * BM;
    const int n0 = blockIdx.x * BN;

    float acc[8][8];
    #pragma unroll
    for (int i = 0; i < 8; i++)
        #pragma unroll
        for (int j = 0; j < 8; j++) acc[i][j] = 0.f;

    for (int k0 = 0; k0 < K; k0 += BK) {
        // --- load A tile (transposed into As[k][m]) ---
        #pragma unroll
        for (int l = 0; l < 2; l++) {
            int f = tid * 2 + l;              // 0..511
            int r = f >> 2;                   // row within tile
            int c4 = (f & 3) * 4;             // k offset
            float4 a = *(const float4*)(A + (size_t)(m0 + r) * lda + k0 + c4);
            if (ABN) {
                a.x = fmaxf(0.f, a.x * aA[k0 + c4 + 0] + aB[k0 + c4 + 0]);
                a.y = fmaxf(0.f, a.y * aA[k0 + c4 + 1] + aB[k0 + c4 + 1]);
                a.z = fmaxf(0.f, a.z * aA[k0 + c4 + 2] + aB[k0 + c4 + 2]);
                a.w = fmaxf(0.f, a.w * aA[k0 + c4 + 3] + aB[k0 + c4 + 3]);
            }
            As[c4 + 0][r] = a.x; As[c4 + 1][r] = a.y;
            As[c4 + 2][r] = a.z; As[c4 + 3][r] = a.w;
        }
        // --- load B tile into Bs[k][n] ---
        if (MODEB == 0) {
            #pragma unroll
            for (int l = 0; l < 2; l++) {
                int f = tid * 2 + l;
                int r = f >> 2;               // n within tile
                int c4 = (f & 3) * 4;         // k offset
                float4 b = *(const float4*)(Bm + (size_t)(n0 + r) * ldb + k0 + c4);
                Bs[c4 + 0][r] = b.x; Bs[c4 + 1][r] = b.y;
                Bs[c4 + 2][r] = b.z; Bs[c4 + 3][r] = b.w;
            }
        } else {
            #pragma unroll
            for (int l = 0; l < 2; l++) {
                int f = tid * 2 + l;
                int r = f >> 5;               // k within tile (0..15)
                int c = (f & 31) * 4;         // n offset
                *(float4*)(&Bs[r][c]) =
                    *(const float4*)(Bm + (size_t)(k0 + r) * ldb + n0 + c);
            }
        }
        __syncthreads();

        #pragma unroll
        for (int k = 0; k < BK; k++) {
            float a[8], b[8];
            *(float4*)(a)     = *(const float4*)(&As[k][ty * 8]);
            *(float4*)(a + 4) = *(const float4*)(&As[k][ty * 8 + 4]);
            *(float4*)(b)     = *(const float4*)(&Bs[k][tx * 8]);
            *(float4*)(b + 4) = *(const float4*)(&Bs[k][tx * 8 + 4]);
            #pragma unroll
            for (int i = 0; i < 8; i++)
                #pragma unroll
                for (int j = 0; j < 8; j++)
                    acc[i][j] += a[i] * b[j];
        }
        __syncthreads();
    }

    // --- epilogue ---
    #pragma unroll
    for (int i = 0; i < 8; i++) {
        int m = m0 + ty * 8 + i;
        #pragma unroll
        for (int j = 0; j < 8; j++) {
            int n = n0 + tx * 8 + j;
            float v = acc[i][j];
            if (EPI == 1) {
                v = fmaxf(0.f, lzp[(size_t)m * N + n] +
                               sqrtf(fmaxf(v, 0.f)) + pbias[n]);
            } else if (EPI == 2) {
                v += bias[n];
            }
            acc[i][j] = v;
        }
        float* cp = C + (size_t)m * N + n0 + tx * 8;
        *(float4*)(cp)     = make_float4(acc[i][0], acc[i][1], acc[i][2], acc[i][3]);
        *(float4*)(cp + 4) = make_float4(acc[i][4], acc[i][5], acc[i][6], acc[i][7]);
    }

    if (EPI == 2) {
        // deterministic per-block column partials (no atomics)
        __syncthreads();
        float* redS = &As[0][0];   // 2048 floats = 16 x 128
        float* redQ = &Bs[0][0];
        #pragma unroll
        for (int j = 0; j < 8; j++) {
            float s = 0.f, q = 0.f;
            #pragma unroll
            for (int i = 0; i < 8; i++) { float v = acc[i][j]; s += v; q += v * v; }
            redS[ty * 128 + tx * 8 + j] = s;
            redQ[ty * 128 + tx * 8 + j] = q;
        }
        __syncthreads();
        if (tid < 128) {
            float s = 0.f, q = 0.f;
            #pragma unroll
            for (int t = 0; t < 16; t++) {
                s += redS[t * 128 + tid];
                q += redQ[t * 128 + tid];
            }
            statS[blockIdx.y * N + n0 + tid] = s;
            statQ[blockIdx.y * N + n0 + tid] = q;
        }
    }
}

// ---------------- BN finalize: per-column affine params --------------------
__global__ void bnfin_kernel(const float* __restrict__ pS,
                             const float* __restrict__ pQ, int H,
                             const float* __restrict__ scale,
                             const float* __restrict__ offset,
                             float* __restrict__ oA, float* __restrict__ oB) {
    int c = blockIdx.x * blockDim.x + threadIdx.x;
    if (c >= H) return;
    float s = 0.f, q = 0.f;
    for (int t = 0; t < 128; t++) { s += pS[t * H + c]; q += pQ[t * H + c]; }
    float m = s * (1.f / (float)BATCH);
    float v = q * (1.f / (float)BATCH) - m * m;
    float a = scale[0] * rsqrtf(fmaxf(v, 0.f) + 1e-10f);
    oA[c] = a;
    oB[c] = offset[0] - m * a;
}

// ---------------- output head ----------------------------------------------
__global__ void out_kernel(const float* __restrict__ w,
                           const float* __restrict__ ob,
                           float* __restrict__ out) {
    int b = blockIdx.x;
    int tid = threadIdx.x;   // 128 threads
    const float* row = g_y2 + (size_t)b * HH2;
    float s = 0.f;
    #pragma unroll
    for (int n = tid; n < HH2; n += 128) {
        float v = fmaxf(0.f, row[n] * g_bnA2[n] + g_bnB2[n]);
        s += v * w[n];
    }
    __shared__ float red[128];
    red[tid] = s;
    __syncthreads();
    for (int off = 64; off > 0; off >>= 1) {
        if (tid < off) red[tid] += red[tid + off];
        __syncthreads();
    }
    if (tid == 0) {
        float x = red[0] + ob[0];
        out[b] = 1.f / (1.f + expf(-x));
    }
}

// ---------------- launch ----------------------------------------------------
extern "C" void kernel_launch(void* const* d_in, const int* in_sizes, int n_in,
                              void* d_out, int out_size) {
    const int*   fidx  = (const int*)  d_in[0];
    const float* fval  = (const float*)d_in[1];
    const float* femb  = (const float*)d_in[2];
    const float* pl    = (const float*)d_in[3];
    const float* pbias = (const float*)d_in[4];
    const float* pq    = (const float*)d_in[5];
    const float* W0    = (const float*)d_in[6];
    const float* b0    = (const float*)d_in[7];
    const float* W1    = (const float*)d_in[8];
    const float* b1    = (const float*)d_in[9];
    const float* bnS   = (const float*)d_in[10];
    const float* bnO   = (const float*)d_in[11];
    const float* ow    = (const float*)d_in[12];
    const float* ob    = (const float*)d_in[13];
    float* out = (float*)d_out;

    void *emb, *gram, *R, *lz, *y0, *y1, *y2, *pS, *pQ, *A1, *B1, *A2, *B2;
    cudaGetSymbolAddress(&emb,  g_emb);
    cudaGetSymbolAddress(&gram, g_gram);
    cudaGetSymbolAddress(&R,    g_R);
    cudaGetSymbolAddress(&lz,   g_lz);
    cudaGetSymbolAddress(&y0,   g_y0);
    cudaGetSymbolAddress(&y1,   g_y1);
    cudaGetSymbolAddress(&y2,   g_y2);
    cudaGetSymbolAddress(&pS,   g_pS);
    cudaGetSymbolAddress(&pQ,   g_pQ);
    cudaGetSymbolAddress(&A1,   g_bnA1);
    cudaGetSymbolAddress(&B1,   g_bnB1);
    cudaGetSymbolAddress(&A2,   g_bnA2);
    cudaGetSymbolAddress(&B2,   g_bnB2);

    // 1) embedding gather
    embed_kernel<<<(BATCH * FF) / 4, 256>>>(fidx, fval, femb);
    // 2) Gram matrices per batch row
    gram_kernel<<<BATCH, 256>>>();
    // 3) R weights from quadratic-inner params
    rk_kernel<<<DD, 256>>>(pq);
    // 4) LZ = emb @ PL^T   (16384 x 512, K=3200)
    gemm_kernel<0, 0, false><<<dim3(DD / BN, BATCH / BM), 256>>>(
        (const float*)emb, pl, (float*)lz, DD, FE, FE, FE,
        nullptr, nullptr, nullptr, nullptr, nullptr, nullptr, nullptr);
    // 5) LP2 = G @ R^T, fused y0 = relu(lz + sqrt(lp2) + pbias)
    gemm_kernel<0, 1, false><<<dim3(DD / BN, BATCH / BM), 256>>>(
        (const float*)gram, (const float*)R, (float*)y0, DD, KPAD, KPAD, KPAD,
        nullptr, nullptr, nullptr, (const float*)lz, pbias, nullptr, nullptr);
    // 6) y1 = y0 @ W0 + b0, with BN stat partials
    gemm_kernel<1, 2, false><<<dim3(HH1 / BN, BATCH / BM), 256>>>(
        (const float*)y0, W0, (float*)y1, HH1, DD, DD, HH1,
        nullptr, nullptr, b0, nullptr, nullptr, (float*)pS, (float*)pQ);
    bnfin_kernel<<<HH1 / 256, 256>>>((const float*)pS, (const float*)pQ, HH1,
                                     bnS, bnO, (float*)A1, (float*)B1);
    // 7) y2 = bnrelu(y1) @ W1 + b1, with BN stat partials
    gemm_kernel<1, 2, true><<<dim3(HH2 / BN, BATCH / BM), 256>>>(
        (const float*)y1, W1, (float*)y2, HH2, HH1, HH1, HH2,
        (const float*)A1, (const float*)B1, b1, nullptr, nullptr,
        (float*)pS, (float*)pQ);
    bnfin_kernel<<<HH2 / 256, 256>>>((const float*)pS, (const float*)pQ, HH2,
                                     bnS, bnO, (float*)A2, (float*)B2);
    // 8) output head
    out_kernel<<<BATCH, 128>>>(ow, ob, out);
}